// round 1
// baseline (speedup 1.0000x reference)
#include <cuda_runtime.h>
#include <cstdint>
#include <math.h>

#define TOKENS 4096
#define HS 1024
#define FFN 4096
#define NE 8
#define CAP 512

// ---------------- scratch (static device globals; no allocations) -----------
__device__ int   g_expert[TOKENS * 2];
__device__ float g_weight[TOKENS * 2];
__device__ int   g_rows[NE * 1024];      // per expert: 512 k=0 slots then 512 k=1 slots; -1 = empty
__device__ int   g_pos[2 * TOKENS];      // token -> row in g_ye (or -1 dropped)
__device__ float g_h[(size_t)NE * 1024 * FFN];   // 134 MB intermediate activations
__device__ float g_ye[(size_t)NE * 1024 * HS];   // 33.5 MB expert outputs

// ---------------- router: warp per token ------------------------------------
__global__ void router_kernel(const float* __restrict__ x, const float* __restrict__ rw) {
    int warp = threadIdx.x >> 5, lane = threadIdx.x & 31;
    int t = blockIdx.x * 8 + warp;
    const float* xr = x + (size_t)t * HS;
    float acc[NE];
#pragma unroll
    for (int e = 0; e < NE; e++) acc[e] = 0.f;
    for (int j = lane; j < HS; j += 32) {
        float xv = xr[j];
        const float4* r4 = reinterpret_cast<const float4*>(rw + (size_t)j * NE);
        float4 ra = r4[0], rb = r4[1];
        acc[0] += xv * ra.x; acc[1] += xv * ra.y; acc[2] += xv * ra.z; acc[3] += xv * ra.w;
        acc[4] += xv * rb.x; acc[5] += xv * rb.y; acc[6] += xv * rb.z; acc[7] += xv * rb.w;
    }
#pragma unroll
    for (int o = 16; o > 0; o >>= 1)
#pragma unroll
        for (int e = 0; e < NE; e++) acc[e] += __shfl_xor_sync(0xffffffffu, acc[e], o);
    if (lane == 0) {
        float m = acc[0];
#pragma unroll
        for (int e = 1; e < NE; e++) m = fmaxf(m, acc[e]);
        float s[NE]; float sum = 0.f;
#pragma unroll
        for (int e = 0; e < NE; e++) { s[e] = expf(acc[e] - m); sum += s[e]; }
        float inv = 1.f / sum;
        int e0 = 0; float m0 = s[0];
#pragma unroll
        for (int e = 1; e < NE; e++) if (s[e] > m0) { m0 = s[e]; e0 = e; }
        int e1 = -1; float m1 = -1.f;
#pragma unroll
        for (int e = 0; e < NE; e++) if (e != e0 && s[e] > m1) { m1 = s[e]; e1 = e; }
        g_expert[t * 2 + 0] = e0; g_expert[t * 2 + 1] = e1;
        g_weight[t * 2 + 0] = m0 * inv; g_weight[t * 2 + 1] = m1 * inv;
    }
}

// ---------------- dispatch: warp per (k, expert), ballot scan ----------------
// Reproduces stable sort-by-expert + capacity drop exactly (token-index order).
__global__ void dispatch_kernel() {
    int w = threadIdx.x >> 5, lane = threadIdx.x & 31;
    int k = w >> 3, e = w & 7;
    int count = 0;
    for (int base = 0; base < TOKENS; base += 32) {
        int t = base + lane;
        int ex = g_expert[t * 2 + k];
        bool match = (ex == e);
        unsigned mask = __ballot_sync(0xffffffffu, match);
        int r = count + __popc(mask & ((1u << lane) - 1u));
        if (match) {
            if (r < CAP) {
                int slot = k * CAP + r;
                g_rows[e * 1024 + slot] = t;
                g_pos[k * TOKENS + t] = e * 1024 + slot;
            } else {
                g_pos[k * TOKENS + t] = -1;   // dropped over capacity
            }
        }
        count += __popc(mask);
    }
    for (int s = count + lane; s < CAP; s += 32)
        g_rows[e * 1024 + k * CAP + s] = -1;
}

// ---------------- tf32 GEMM machinery ----------------------------------------
#define BM 128
#define BN 128
#define BK 32
#define A_STRIDE 36                  // bank-conflict-free fragment loads
#define B_STRIDE 132
#define A_STAGE (BM * A_STRIDE)      // 4608 floats
#define B_STAGE (BK * B_STRIDE)      // 4224 floats
#define SMEM_BYTES ((2 * A_STAGE + 2 * B_STAGE) * 4)

__device__ __forceinline__ void cp16(uint32_t sdst, const float* gsrc, int nbytes) {
    asm volatile("cp.async.cg.shared.global [%0], [%1], 16, %2;\n"
                 :: "r"(sdst), "l"(gsrc), "r"(nbytes));
}
__device__ __forceinline__ void cp_commit() { asm volatile("cp.async.commit_group;\n"); }
template <int N> __device__ __forceinline__ void cp_wait() {
    asm volatile("cp.async.wait_group %0;\n" :: "n"(N));
}
__device__ __forceinline__ uint32_t f2tf32(float f) {
    uint32_t u;
    asm("cvt.rna.tf32.f32 %0, %1;\n" : "=r"(u) : "f"(f));
    return u;
}
__device__ __forceinline__ void mma_tf32(float c[4], const uint32_t a[4], const uint32_t b[2]) {
    asm volatile(
        "mma.sync.aligned.m16n8k8.row.col.f32.tf32.tf32.f32 "
        "{%0,%1,%2,%3}, {%4,%5,%6,%7}, {%8,%9}, {%0,%1,%2,%3};\n"
        : "+f"(c[0]), "+f"(c[1]), "+f"(c[2]), "+f"(c[3])
        : "r"(a[0]), "r"(a[1]), "r"(a[2]), "r"(a[3]), "r"(b[0]), "r"(b[1]));
}
__device__ __forceinline__ float gelu_tanh(float v) {
    float v3 = v * v * v;
    return 0.5f * v * (1.0f + tanhf(0.7978845608028654f * (v + 0.044715f * v3)));
}

// FIRST: C[e,1024,FFN] = gelu(gather(X)[e,1024,HS] @ w1[e])   (A gathered via g_rows, zfill)
// !FIRST: C[e,1024,HS]  = g_h[e] @ w2[e]
template <bool FIRST>
__global__ void __launch_bounds__(256)
gemm_kernel(const float* __restrict__ X, const float* __restrict__ W) {
    constexpr int K = FIRST ? HS : FFN;
    constexpr int N = FIRST ? FFN : HS;
    constexpr int KT = K / BK;
    extern __shared__ float smem[];
    float* As = smem;
    float* Bs = smem + 2 * A_STAGE;
    const int e = blockIdx.z;
    const int tid = threadIdx.x;

    const float* Abase = FIRST ? X : (g_h + (size_t)e * 1024 * FFN);
    const float* Bbase = W + (size_t)e * K * N;

    const float* aSrc[4]; int aSz[4]; uint32_t aDst[4];
    const float* bSrc[4]; uint32_t bDst[4];
#pragma unroll
    for (int i = 0; i < 4; i++) {
        int cid = tid + i * 256;
        int row = cid >> 3;            // 0..127
        int kc  = (cid & 7) * 4;       // 0..28
        const float* src; int sz = 16;
        if (FIRST) {
            int gr = g_rows[e * 1024 + blockIdx.y * BM + row];
            if (gr < 0) { sz = 0; src = Abase; }
            else        { src = Abase + (size_t)gr * K + kc; }
        } else {
            src = Abase + (size_t)(blockIdx.y * BM + row) * K + kc;
        }
        aSrc[i] = src; aSz[i] = sz;
        aDst[i] = (uint32_t)__cvta_generic_to_shared(As + row * A_STRIDE + kc);
        int kr = cid >> 5;             // 0..31
        int nc = (cid & 31) * 4;       // 0..124
        bSrc[i] = Bbase + (size_t)kr * N + blockIdx.x * BN + nc;
        bDst[i] = (uint32_t)__cvta_generic_to_shared(Bs + kr * B_STRIDE + nc);
    }

    const int lane = tid & 31, wid = tid >> 5;
    const int wm = wid & 1, wn = wid >> 1;        // 2x4 warp grid, 64x32 per warp
    const int grp = lane >> 2, qid = lane & 3;

    float c[4][4][4];
#pragma unroll
    for (int mt = 0; mt < 4; mt++)
#pragma unroll
        for (int nt = 0; nt < 4; nt++)
#pragma unroll
            for (int r = 0; r < 4; r++) c[mt][nt][r] = 0.f;

    // prologue load
    {
#pragma unroll
        for (int i = 0; i < 4; i++) cp16(aDst[i], aSrc[i], aSz[i]);
#pragma unroll
        for (int i = 0; i < 4; i++) cp16(bDst[i], bSrc[i], 16);
        cp_commit();
    }

    for (int kt = 0; kt < KT; kt++) {
        int s = kt & 1;
        if (kt + 1 < KT) {
            int s2 = s ^ 1;
#pragma unroll
            for (int i = 0; i < 4; i++)
                cp16(aDst[i] + s2 * A_STAGE * 4, aSrc[i] + (kt + 1) * BK, aSz[i]);
#pragma unroll
            for (int i = 0; i < 4; i++)
                cp16(bDst[i] + s2 * B_STAGE * 4, bSrc[i] + (size_t)(kt + 1) * BK * N, 16);
            cp_commit();
            cp_wait<1>();
        } else {
            cp_wait<0>();
        }
        __syncthreads();

        const float* As_ = As + s * A_STAGE;
        const float* Bs_ = Bs + s * B_STAGE;
#pragma unroll
        for (int kk = 0; kk < 4; kk++) {
            const int k0 = kk * 8;
            uint32_t af[4][4];
#pragma unroll
            for (int mt = 0; mt < 4; mt++) {
                const float* ap = As_ + (wm * 64 + mt * 16 + grp) * A_STRIDE + k0 + qid;
                af[mt][0] = f2tf32(ap[0]);
                af[mt][1] = f2tf32(ap[8 * A_STRIDE]);
                af[mt][2] = f2tf32(ap[4]);
                af[mt][3] = f2tf32(ap[8 * A_STRIDE + 4]);
            }
            uint32_t bf[4][2];
#pragma unroll
            for (int nt = 0; nt < 4; nt++) {
                const float* bp = Bs_ + (k0 + qid) * B_STRIDE + wn * 32 + nt * 8 + grp;
                bf[nt][0] = f2tf32(bp[0]);
                bf[nt][1] = f2tf32(bp[4 * B_STRIDE]);
            }
#pragma unroll
            for (int mt = 0; mt < 4; mt++)
#pragma unroll
                for (int nt = 0; nt < 4; nt++)
                    mma_tf32(c[mt][nt], af[mt], bf[nt]);
        }
        __syncthreads();
    }

    // epilogue
    float* Cbase = FIRST ? g_h : g_ye;
    size_t rowBase = (size_t)e * 1024 + blockIdx.y * BM + wm * 64;
    int colBase = blockIdx.x * BN + wn * 32;
#pragma unroll
    for (int mt = 0; mt < 4; mt++) {
#pragma unroll
        for (int nt = 0; nt < 4; nt++) {
            size_t r0 = rowBase + mt * 16 + grp;
            int cc = colBase + nt * 8 + qid * 2;
            float v0 = c[mt][nt][0], v1 = c[mt][nt][1], v2 = c[mt][nt][2], v3 = c[mt][nt][3];
            if (FIRST) {
                v0 = gelu_tanh(v0); v1 = gelu_tanh(v1);
                v2 = gelu_tanh(v2); v3 = gelu_tanh(v3);
            }
            float* p0 = Cbase + r0 * N + cc;
            float* p1 = Cbase + (r0 + 8) * N + cc;
            p0[0] = v0; p0[1] = v1;
            p1[0] = v2; p1[1] = v3;
        }
    }
}

// ---------------- combine: out = bias + sum_k weight * ye[pos] ---------------
__global__ void combine_kernel(const float* __restrict__ bias, float* __restrict__ out) {
    int t = blockIdx.x;
    int j = threadIdx.x;  // 256 threads x float4 = 1024 floats
    float4 acc = reinterpret_cast<const float4*>(bias)[j];
    int p0 = g_pos[t];
    int p1 = g_pos[TOKENS + t];
    float w0 = g_weight[t * 2 + 0], w1 = g_weight[t * 2 + 1];
    if (p0 >= 0) {
        float4 v = reinterpret_cast<const float4*>(g_ye + (size_t)p0 * HS)[j];
        acc.x += w0 * v.x; acc.y += w0 * v.y; acc.z += w0 * v.z; acc.w += w0 * v.w;
    }
    if (p1 >= 0) {
        float4 v = reinterpret_cast<const float4*>(g_ye + (size_t)p1 * HS)[j];
        acc.x += w1 * v.x; acc.y += w1 * v.y; acc.z += w1 * v.z; acc.w += w1 * v.w;
    }
    reinterpret_cast<float4*>(out + (size_t)t * HS)[j] = acc;
}

// ---------------- launch ------------------------------------------------------
extern "C" void kernel_launch(void* const* d_in, const int* in_sizes, int n_in,
                              void* d_out, int out_size) {
    const float* x    = (const float*)d_in[0];
    const float* rw   = (const float*)d_in[1];
    const float* w1   = (const float*)d_in[2];
    const float* w2   = (const float*)d_in[3];
    const float* bias = (const float*)d_in[4];
    float* out = (float*)d_out;

    cudaFuncSetAttribute(gemm_kernel<true>,  cudaFuncAttributeMaxDynamicSharedMemorySize, SMEM_BYTES);
    cudaFuncSetAttribute(gemm_kernel<false>, cudaFuncAttributeMaxDynamicSharedMemorySize, SMEM_BYTES);

    router_kernel<<<TOKENS / 8, 256>>>(x, rw);
    dispatch_kernel<<<1, 512>>>();
    gemm_kernel<true ><<<dim3(FFN / BN, 1024 / BM, NE), 256, SMEM_BYTES>>>(x, w1);
    gemm_kernel<false><<<dim3(HS  / BN, 1024 / BM, NE), 256, SMEM_BYTES>>>(nullptr, w2);
    combine_kernel<<<TOKENS, 256>>>(bias, out);
}

// round 3
// speedup vs baseline: 1.1778x; 1.1778x over previous
#include <cuda_runtime.h>
#include <cuda_fp16.h>
#include <cstdint>
#include <math.h>

#define TOKENS 4096
#define HS 1024
#define FFN 4096
#define NE 8
#define CAP 512

// ---------------- scratch (static device globals; no allocations) -----------
__device__ int    g_expert[TOKENS * 2];
__device__ float  g_weight[TOKENS * 2];
__device__ int    g_rows[NE * 1024];
__device__ int    g_pos[2 * TOKENS];
__device__ __half g_h[(size_t)NE * 1024 * FFN];   // GEMM1 out, fp16 (67MB)
__device__ float  g_ye[(size_t)NE * 1024 * HS];   // GEMM2 out, f32

// ---------------- GEMM config -------------------------------------------------
#define BM 256
#define BN 128
#define BK 32
#define NTH 512
#define A_STAGE 16384            // 256 rows x 64B (32 fp16)
#define B_STAGE 8192             // 32 rows x 256B (128 fp16)
#define SM_B0 (2 * A_STAGE)      // 32768
#define SMEM_TOT (SM_B0 + 2 * B_STAGE)   // 49152
#define SLAB 2304                // 16x36 f32 per-warp epilogue slab

// ---------------- helpers -----------------------------------------------------
__device__ __forceinline__ uint32_t smem_u32(const void* p) {
    uint32_t a;
    asm("{ .reg .u64 t; cvta.to.shared.u64 t, %1; cvt.u32.u64 %0, t; }" : "=r"(a) : "l"(p));
    return a;
}
__device__ __forceinline__ uint32_t pack2(float lo, float hi) {
    __half2 h = __floats2half2_rn(lo, hi);
    return *reinterpret_cast<uint32_t*>(&h);
}
__device__ __forceinline__ void ldsm4(uint32_t r[4], uint32_t addr) {
    asm volatile("ldmatrix.sync.aligned.m8n8.x4.shared.b16 {%0,%1,%2,%3}, [%4];"
                 : "=r"(r[0]), "=r"(r[1]), "=r"(r[2]), "=r"(r[3]) : "r"(addr));
}
__device__ __forceinline__ void ldsm4t(uint32_t r[4], uint32_t addr) {
    asm volatile("ldmatrix.sync.aligned.m8n8.x4.trans.shared.b16 {%0,%1,%2,%3}, [%4];"
                 : "=r"(r[0]), "=r"(r[1]), "=r"(r[2]), "=r"(r[3]) : "r"(addr));
}
__device__ __forceinline__ void mma16816(float c[4], const uint32_t a[4],
                                         uint32_t b0, uint32_t b1) {
    asm volatile(
        "mma.sync.aligned.m16n8k16.row.col.f32.f16.f16.f32 "
        "{%0,%1,%2,%3}, {%4,%5,%6,%7}, {%8,%9}, {%0,%1,%2,%3};"
        : "+f"(c[0]), "+f"(c[1]), "+f"(c[2]), "+f"(c[3])
        : "r"(a[0]), "r"(a[1]), "r"(a[2]), "r"(a[3]), "r"(b0), "r"(b1));
}
__device__ __forceinline__ float gelu_tanh(float v) {
    float v3 = v * v * v;
    return 0.5f * v * (1.0f + tanhf(0.7978845608028654f * (v + 0.044715f * v3)));
}

// ---------------- router: warp per token (validated R1) -----------------------
__global__ void router_kernel(const float* __restrict__ x, const float* __restrict__ rw) {
    int warp = threadIdx.x >> 5, lane = threadIdx.x & 31;
    int t = blockIdx.x * 8 + warp;
    const float* xr = x + (size_t)t * HS;
    float acc[NE];
#pragma unroll
    for (int e = 0; e < NE; e++) acc[e] = 0.f;
    for (int j = lane; j < HS; j += 32) {
        float xv = xr[j];
        const float4* r4 = reinterpret_cast<const float4*>(rw + (size_t)j * NE);
        float4 ra = r4[0], rb = r4[1];
        acc[0] += xv * ra.x; acc[1] += xv * ra.y; acc[2] += xv * ra.z; acc[3] += xv * ra.w;
        acc[4] += xv * rb.x; acc[5] += xv * rb.y; acc[6] += xv * rb.z; acc[7] += xv * rb.w;
    }
#pragma unroll
    for (int o = 16; o > 0; o >>= 1)
#pragma unroll
        for (int e = 0; e < NE; e++) acc[e] += __shfl_xor_sync(0xffffffffu, acc[e], o);
    if (lane == 0) {
        float m = acc[0];
#pragma unroll
        for (int e = 1; e < NE; e++) m = fmaxf(m, acc[e]);
        float s[NE]; float sum = 0.f;
#pragma unroll
        for (int e = 0; e < NE; e++) { s[e] = expf(acc[e] - m); sum += s[e]; }
        float inv = 1.f / sum;
        int e0 = 0; float m0 = s[0];
#pragma unroll
        for (int e = 1; e < NE; e++) if (s[e] > m0) { m0 = s[e]; e0 = e; }
        int e1 = -1; float m1 = -1.f;
#pragma unroll
        for (int e = 0; e < NE; e++) if (e != e0 && s[e] > m1) { m1 = s[e]; e1 = e; }
        g_expert[t * 2 + 0] = e0; g_expert[t * 2 + 1] = e1;
        g_weight[t * 2 + 0] = m0 * inv; g_weight[t * 2 + 1] = m1 * inv;
    }
}

// ---------------- dispatch (validated R1) -------------------------------------
__global__ void dispatch_kernel() {
    int w = threadIdx.x >> 5, lane = threadIdx.x & 31;
    int k = w >> 3, e = w & 7;
    int count = 0;
    for (int base = 0; base < TOKENS; base += 32) {
        int t = base + lane;
        int ex = g_expert[t * 2 + k];
        bool match = (ex == e);
        unsigned mask = __ballot_sync(0xffffffffu, match);
        int r = count + __popc(mask & ((1u << lane) - 1u));
        if (match) {
            if (r < CAP) {
                int slot = k * CAP + r;
                g_rows[e * 1024 + slot] = t;
                g_pos[k * TOKENS + t] = e * 1024 + slot;
            } else {
                g_pos[k * TOKENS + t] = -1;
            }
        }
        count += __popc(mask);
    }
    for (int s = count + lane; s < CAP; s += 32)
        g_rows[e * 1024 + k * CAP + s] = -1;
}

// ---------------- fp16 mma GEMM ------------------------------------------------
// FIRST: g_h[e, yb*256.., :FFN] = fp16(gelu(gather(X) @ w1[e]))
// else : g_ye[e, yb*256.., :HS] = g_h @ w2[e]
template <bool FIRST>
__global__ void __launch_bounds__(NTH, 1)
moe_gemm(const float* __restrict__ X, const float* __restrict__ W) {
    constexpr int K = FIRST ? HS : FFN;
    constexpr int N = FIRST ? FFN : HS;
    constexpr int KT = K / BK;
    extern __shared__ char smem[];
    const uint32_t sbase = smem_u32(smem);
    const int tid = threadIdx.x, wid = tid >> 5, lane = tid & 31;
    const int e = blockIdx.z, by = blockIdx.y, nb = blockIdx.x;
    const int wm = wid & 3, wn = wid >> 2;         // 4x4 warp grid, 64x32/warp
    const int grp = lane >> 2, qid = lane & 3;

    // ---- staging setup ----
    const int ar = tid & 255, hk = tid >> 8;       // A: row, k-half
    const float* aSrcF = nullptr; const __half* aSrcH = nullptr;
    bool aval = true;
    if (FIRST) {
        int tok = g_rows[e * 1024 + by * 256 + ar];
        aval = (tok >= 0);
        aSrcF = X + (size_t)(aval ? tok : 0) * HS + hk * 16;
    } else {
        aSrcH = g_h + (size_t)(e * 1024 + by * 256 + ar) * FFN + hk * 16;
    }
    const int aswz = (ar >> 1) & 3;
    const int aOff0 = ar * 64 + (((hk * 2 + 0) ^ aswz) << 4);
    const int aOff1 = ar * 64 + (((hk * 2 + 1) ^ aswz) << 4);
    const int br = tid >> 4, bc = tid & 15;        // B: k-row, n-chunk
    const float* bSrc = W + (size_t)e * K * N + (size_t)br * N + nb * BN + bc * 8;
    const int bOff = SM_B0 + br * 256 + ((bc ^ (br & 7)) << 4);

    // ---- ldmatrix base addresses (per lane) ----
    uint32_t aA, bA;
    {
        int r = wm * 64 + (lane & 15);
        int c = (lane >> 4);
        aA = sbase + r * 64 + ((c ^ ((r >> 1) & 3)) << 4);
        int k = (lane & 15);
        int cb = wn * 4 + (lane >> 4);
        bA = sbase + SM_B0 + k * 256 + ((cb ^ (k & 7)) << 4);
    }

    float c[4][4][4];
#pragma unroll
    for (int mf = 0; mf < 4; mf++)
#pragma unroll
        for (int nn = 0; nn < 4; nn++)
#pragma unroll
            for (int i = 0; i < 4; i++) c[mf][nn][i] = 0.f;

    uint32_t aH[2][4], bH[4];

    auto load_regs = [&](int kt) {
        if (FIRST) {
#pragma unroll
            for (int j = 0; j < 2; j++) {
                float4 f0, f1;
                if (aval) {
                    f0 = *reinterpret_cast<const float4*>(aSrcF + kt * BK + j * 8);
                    f1 = *reinterpret_cast<const float4*>(aSrcF + kt * BK + j * 8 + 4);
                } else {
                    f0 = make_float4(0.f, 0.f, 0.f, 0.f); f1 = f0;
                }
                aH[j][0] = pack2(f0.x, f0.y); aH[j][1] = pack2(f0.z, f0.w);
                aH[j][2] = pack2(f1.x, f1.y); aH[j][3] = pack2(f1.z, f1.w);
            }
        } else {
#pragma unroll
            for (int j = 0; j < 2; j++) {
                uint4 v = *reinterpret_cast<const uint4*>(aSrcH + kt * BK + j * 8);
                aH[j][0] = v.x; aH[j][1] = v.y; aH[j][2] = v.z; aH[j][3] = v.w;
            }
        }
        const float* bp = bSrc + (size_t)kt * BK * N;
        float4 g0 = *reinterpret_cast<const float4*>(bp);
        float4 g1 = *reinterpret_cast<const float4*>(bp + 4);
        bH[0] = pack2(g0.x, g0.y); bH[1] = pack2(g0.z, g0.w);
        bH[2] = pack2(g1.x, g1.y); bH[3] = pack2(g1.z, g1.w);
    };
    auto store_stage = [&](int s) {
        char* ab = smem + s * A_STAGE;
        *reinterpret_cast<uint4*>(ab + aOff0) = make_uint4(aH[0][0], aH[0][1], aH[0][2], aH[0][3]);
        *reinterpret_cast<uint4*>(ab + aOff1) = make_uint4(aH[1][0], aH[1][1], aH[1][2], aH[1][3]);
        *reinterpret_cast<uint4*>(smem + bOff + s * B_STAGE) = make_uint4(bH[0], bH[1], bH[2], bH[3]);
    };

    // ---- prologue ----
    load_regs(0);
    store_stage(0);
    __syncthreads();

    // ---- mainloop ----
    for (int kt = 0; kt < KT; kt++) {
        const int s = kt & 1;
        if (kt + 1 < KT) load_regs(kt + 1);
        const uint32_t sA = aA + s * A_STAGE;
        const uint32_t sB = bA + s * B_STAGE;
#pragma unroll
        for (int kh = 0; kh < 2; kh++) {
            uint32_t a[4][4];
#pragma unroll
            for (int mf = 0; mf < 4; mf++)
                ldsm4(a[mf], (sA + mf * 1024) ^ (kh << 5));
#pragma unroll
            for (int nf = 0; nf < 2; nf++) {
                uint32_t b[4];
                ldsm4t(b, (sB + kh * 4096) ^ (nf << 5));
#pragma unroll
                for (int mf = 0; mf < 4; mf++) {
                    mma16816(c[mf][nf * 2 + 0], a[mf], b[0], b[1]);
                    mma16816(c[mf][nf * 2 + 1], a[mf], b[2], b[3]);
                }
            }
        }
        if (kt + 1 < KT) store_stage(s ^ 1);
        __syncthreads();
    }

    // ---- epilogue: per-warp smem slab -> coalesced global stores ----
    float* slab = reinterpret_cast<float*>(smem + wid * SLAB);
    const int er = lane >> 1, ec = (lane & 1) * 16;
#pragma unroll
    for (int mf = 0; mf < 4; mf++) {
#pragma unroll
        for (int nn = 0; nn < 4; nn++)
#pragma unroll
            for (int i = 0; i < 4; i++) {
                float v = c[mf][nn][i];
                if (FIRST) v = gelu_tanh(v);
                slab[(grp + (i >> 1) * 8) * 36 + nn * 8 + qid * 2 + (i & 1)] = v;
            }
        __syncwarp();
        float4 v0 = *reinterpret_cast<const float4*>(slab + er * 36 + ec + 0);
        float4 v1 = *reinterpret_cast<const float4*>(slab + er * 36 + ec + 4);
        float4 v2 = *reinterpret_cast<const float4*>(slab + er * 36 + ec + 8);
        float4 v3 = *reinterpret_cast<const float4*>(slab + er * 36 + ec + 12);
        size_t row = (size_t)e * 1024 + by * 256 + wm * 64 + mf * 16 + er;
        int col = nb * BN + wn * 32 + ec;
        if (FIRST) {
            uint4 h0 = make_uint4(pack2(v0.x, v0.y), pack2(v0.z, v0.w),
                                  pack2(v1.x, v1.y), pack2(v1.z, v1.w));
            uint4 h1 = make_uint4(pack2(v2.x, v2.y), pack2(v2.z, v2.w),
                                  pack2(v3.x, v3.y), pack2(v3.z, v3.w));
            uint4* dst = reinterpret_cast<uint4*>(g_h + row * FFN + col);
            dst[0] = h0; dst[1] = h1;
        } else {
            float4* dst = reinterpret_cast<float4*>(g_ye + row * HS + col);
            dst[0] = v0; dst[1] = v1; dst[2] = v2; dst[3] = v3;
        }
        __syncwarp();
    }
}

// ---------------- combine ------------------------------------------------------
__global__ void combine_kernel(const float* __restrict__ bias, float* __restrict__ out) {
    int t = blockIdx.x;
    int j = threadIdx.x;
    float4 acc = reinterpret_cast<const float4*>(bias)[j];
    int p0 = g_pos[t];
    int p1 = g_pos[TOKENS + t];
    float w0 = g_weight[t * 2 + 0], w1 = g_weight[t * 2 + 1];
    if (p0 >= 0) {
        float4 v = reinterpret_cast<const float4*>(g_ye + (size_t)p0 * HS)[j];
        acc.x += w0 * v.x; acc.y += w0 * v.y; acc.z += w0 * v.z; acc.w += w0 * v.w;
    }
    if (p1 >= 0) {
        float4 v = reinterpret_cast<const float4*>(g_ye + (size_t)p1 * HS)[j];
        acc.x += w1 * v.x; acc.y += w1 * v.y; acc.z += w1 * v.z; acc.w += w1 * v.w;
    }
    reinterpret_cast<float4*>(out + (size_t)t * HS)[j] = acc;
}

// ---------------- launch --------------------------------------------------------
extern "C" void kernel_launch(void* const* d_in, const int* in_sizes, int n_in,
                              void* d_out, int out_size) {
    const float* x    = (const float*)d_in[0];
    const float* rw   = (const float*)d_in[1];
    const float* w1   = (const float*)d_in[2];
    const float* w2   = (const float*)d_in[3];
    const float* bias = (const float*)d_in[4];
    float* out = (float*)d_out;

    cudaFuncSetAttribute(moe_gemm<true>,  cudaFuncAttributeMaxDynamicSharedMemorySize, SMEM_TOT);
    cudaFuncSetAttribute(moe_gemm<false>, cudaFuncAttributeMaxDynamicSharedMemorySize, SMEM_TOT);

    router_kernel<<<TOKENS / 8, 256>>>(x, rw);
    dispatch_kernel<<<1, 512>>>();
    moe_gemm<true ><<<dim3(FFN / BN, 1024 / BM, NE), NTH, SMEM_TOT>>>(x, w1);
    moe_gemm<false><<<dim3(HS  / BN, 1024 / BM, NE), NTH, SMEM_TOT>>>(nullptr, w2);
    combine_kernel<<<TOKENS, 256>>>(bias, out);
}

// round 4
// speedup vs baseline: 1.9389x; 1.6462x over previous
#include <cuda_runtime.h>
#include <cuda_fp16.h>
#include <cstdint>
#include <math.h>

#define TOKENS 4096
#define HS 1024
#define FFN 4096
#define NE 8
#define CAP 512

// ---------------- scratch (static device globals; no allocations) -----------
__device__ int    g_expert[TOKENS * 2];
__device__ float  g_weight[TOKENS * 2];
__device__ int    g_rows[NE * 1024];
__device__ int    g_pos[2 * TOKENS];
__device__ __half g_xa[(size_t)NE * 1024 * HS];    // gathered A for gemm1 (fp16)
__device__ __half g_w1h[(size_t)NE * HS * FFN];    // w1 fp16
__device__ __half g_w2h[(size_t)NE * FFN * HS];    // w2 fp16
__device__ __half g_h[(size_t)NE * 1024 * FFN];    // gemm1 out fp16
__device__ float  g_ye[(size_t)NE * 1024 * HS];    // gemm2 out f32

// ---------------- GEMM config -------------------------------------------------
#define BM 256
#define BN 128
#define BK 32
#define NTH 256
#define STAGES 4
#define A_STAGE 16384            // 256 rows x 64B
#define B_STAGE 8192             // 32 rows x 256B
#define SM_B0 (STAGES * A_STAGE) // 65536
#define SMEM_TOT (SM_B0 + STAGES * B_STAGE)  // 98304
#define SLABW 68                 // epilogue slab row width (f32) per warp
#define SLABB (16 * SLABW * 4)   // 4352 bytes per warp

// ---------------- helpers -----------------------------------------------------
__device__ __forceinline__ uint32_t smem_u32(const void* p) {
    uint32_t a;
    asm("{ .reg .u64 t; cvta.to.shared.u64 t, %1; cvt.u32.u64 %0, t; }" : "=r"(a) : "l"(p));
    return a;
}
__device__ __forceinline__ uint32_t pack2(float lo, float hi) {
    __half2 h = __floats2half2_rn(lo, hi);
    return *reinterpret_cast<uint32_t*>(&h);
}
__device__ __forceinline__ void cp16(uint32_t sdst, const void* gsrc) {
    asm volatile("cp.async.cg.shared.global [%0], [%1], 16;" :: "r"(sdst), "l"(gsrc));
}
__device__ __forceinline__ void cp_commit() { asm volatile("cp.async.commit_group;"); }
template <int N> __device__ __forceinline__ void cp_wait() {
    asm volatile("cp.async.wait_group %0;" :: "n"(N));
}
__device__ __forceinline__ void ldsm4(uint32_t r[4], uint32_t addr) {
    asm volatile("ldmatrix.sync.aligned.m8n8.x4.shared.b16 {%0,%1,%2,%3}, [%4];"
                 : "=r"(r[0]), "=r"(r[1]), "=r"(r[2]), "=r"(r[3]) : "r"(addr));
}
__device__ __forceinline__ void ldsm4t(uint32_t r[4], uint32_t addr) {
    asm volatile("ldmatrix.sync.aligned.m8n8.x4.trans.shared.b16 {%0,%1,%2,%3}, [%4];"
                 : "=r"(r[0]), "=r"(r[1]), "=r"(r[2]), "=r"(r[3]) : "r"(addr));
}
__device__ __forceinline__ void mma16816(float c[4], const uint32_t a[4],
                                         uint32_t b0, uint32_t b1) {
    asm volatile(
        "mma.sync.aligned.m16n8k16.row.col.f32.f16.f16.f32 "
        "{%0,%1,%2,%3}, {%4,%5,%6,%7}, {%8,%9}, {%0,%1,%2,%3};"
        : "+f"(c[0]), "+f"(c[1]), "+f"(c[2]), "+f"(c[3])
        : "r"(a[0]), "r"(a[1]), "r"(a[2]), "r"(a[3]), "r"(b0), "r"(b1));
}
__device__ __forceinline__ float gelu_tanh(float v) {
    float v3 = v * v * v;
    return 0.5f * v * (1.0f + tanhf(0.7978845608028654f * (v + 0.044715f * v3)));
}

// ---------------- router (validated) -------------------------------------------
__global__ void router_kernel(const float* __restrict__ x, const float* __restrict__ rw) {
    int warp = threadIdx.x >> 5, lane = threadIdx.x & 31;
    int t = blockIdx.x * 8 + warp;
    const float* xr = x + (size_t)t * HS;
    float acc[NE];
#pragma unroll
    for (int e = 0; e < NE; e++) acc[e] = 0.f;
    for (int j = lane; j < HS; j += 32) {
        float xv = xr[j];
        const float4* r4 = reinterpret_cast<const float4*>(rw + (size_t)j * NE);
        float4 ra = r4[0], rb = r4[1];
        acc[0] += xv * ra.x; acc[1] += xv * ra.y; acc[2] += xv * ra.z; acc[3] += xv * ra.w;
        acc[4] += xv * rb.x; acc[5] += xv * rb.y; acc[6] += xv * rb.z; acc[7] += xv * rb.w;
    }
#pragma unroll
    for (int o = 16; o > 0; o >>= 1)
#pragma unroll
        for (int e = 0; e < NE; e++) acc[e] += __shfl_xor_sync(0xffffffffu, acc[e], o);
    if (lane == 0) {
        float m = acc[0];
#pragma unroll
        for (int e = 1; e < NE; e++) m = fmaxf(m, acc[e]);
        float s[NE]; float sum = 0.f;
#pragma unroll
        for (int e = 0; e < NE; e++) { s[e] = expf(acc[e] - m); sum += s[e]; }
        float inv = 1.f / sum;
        int e0 = 0; float m0 = s[0];
#pragma unroll
        for (int e = 1; e < NE; e++) if (s[e] > m0) { m0 = s[e]; e0 = e; }
        int e1 = -1; float m1 = -1.f;
#pragma unroll
        for (int e = 0; e < NE; e++) if (e != e0 && s[e] > m1) { m1 = s[e]; e1 = e; }
        g_expert[t * 2 + 0] = e0; g_expert[t * 2 + 1] = e1;
        g_weight[t * 2 + 0] = m0 * inv; g_weight[t * 2 + 1] = m1 * inv;
    }
}

// ---------------- dispatch (validated) ------------------------------------------
__global__ void dispatch_kernel() {
    int w = threadIdx.x >> 5, lane = threadIdx.x & 31;
    int k = w >> 3, e = w & 7;
    int count = 0;
    for (int base = 0; base < TOKENS; base += 32) {
        int t = base + lane;
        int ex = g_expert[t * 2 + k];
        bool match = (ex == e);
        unsigned mask = __ballot_sync(0xffffffffu, match);
        int r = count + __popc(mask & ((1u << lane) - 1u));
        if (match) {
            if (r < CAP) {
                int slot = k * CAP + r;
                g_rows[e * 1024 + slot] = t;
                g_pos[k * TOKENS + t] = e * 1024 + slot;
            } else {
                g_pos[k * TOKENS + t] = -1;
            }
        }
        count += __popc(mask);
    }
    for (int s = count + lane; s < CAP; s += 32)
        g_rows[e * 1024 + k * CAP + s] = -1;
}

// ---------------- f32 -> fp16 weight convert -------------------------------------
__global__ void convert_w(const float* __restrict__ src, __half* __restrict__ dst) {
    int i = blockIdx.x * blockDim.x + threadIdx.x;     // one float4 per thread
    float4 v = reinterpret_cast<const float4*>(src)[i];
    reinterpret_cast<uint2*>(dst)[i] = make_uint2(pack2(v.x, v.y), pack2(v.z, v.w));
}

// ---------------- gather X -> fp16 A for gemm1 -----------------------------------
__global__ void gather_x(const float* __restrict__ X) {
    int slot = blockIdx.x;                  // 0..NE*1024-1
    int tok = g_rows[slot];
    int j = threadIdx.x;                    // 256 threads x float4
    uint2 h = make_uint2(0u, 0u);
    if (tok >= 0) {
        float4 v = reinterpret_cast<const float4*>(X + (size_t)tok * HS)[j];
        h = make_uint2(pack2(v.x, v.y), pack2(v.z, v.w));
    }
    reinterpret_cast<uint2*>(g_xa + (size_t)slot * HS)[j] = h;
}

// ---------------- fp16 cp.async GEMM (256 thr, 8 warps, warp 64x64) --------------
// FIRST: g_h[e, by*256.., :FFN] = fp16(gelu(g_xa @ w1h[e]))
// else : g_ye[e, by*256.., :HS] = g_h @ w2h[e]
template <bool FIRST>
__global__ void __launch_bounds__(NTH, 1)
moe_gemm(const __half* __restrict__ A0, const __half* __restrict__ W0) {
    constexpr int K = FIRST ? HS : FFN;
    constexpr int N = FIRST ? FFN : HS;
    constexpr int KT = K / BK;
    extern __shared__ char smem[];
    const uint32_t sbase = smem_u32(smem);
    const int tid = threadIdx.x, wid = tid >> 5, lane = tid & 31;
    const int e = blockIdx.z, by = blockIdx.y, nb = blockIdx.x;
    const int wm = wid & 3, wn = wid >> 2;          // 4x2 warp grid -> 64x64 per warp
    const int grp = lane >> 2, qid = lane & 3;

    const __half* Abase = A0 + (size_t)(e * 1024 + by * 256) * K;
    const __half* Wbase = W0 + (size_t)e * K * N + nb * BN;

    // cp.async per-thread sources/destinations
    const __half* aSrc = Abase + (size_t)(tid >> 2) * K + (tid & 3) * 8;
    const uint32_t aDst = sbase + (tid >> 2) * 64 + ((((tid & 3)) ^ (((tid >> 2) >> 1) & 3)) << 4);
    const __half* bSrc = Wbase + (size_t)(tid >> 4) * N + (tid & 15) * 8;
    const uint32_t bDst = sbase + SM_B0 + (tid >> 4) * 256 + (((tid & 15) ^ ((tid >> 4) & 7)) << 4);

    auto issue = [&](int kt) {
        const int s = kt & (STAGES - 1);
        const __half* ap = aSrc + kt * BK;
#pragma unroll
        for (int p = 0; p < 4; p++)
            cp16(aDst + s * A_STAGE + p * 4096, ap + (size_t)p * 64 * K);
        const __half* bp = bSrc + (size_t)kt * BK * N;
#pragma unroll
        for (int p = 0; p < 2; p++)
            cp16(bDst + s * B_STAGE + p * 4096, bp + (size_t)p * 16 * N);
    };

    // ldmatrix fragment base addresses
    uint32_t aA, bA;
    {
        int r0 = wm * 64 + (lane & 15);
        int c0 = lane >> 4;
        aA = sbase + r0 * 64 + ((c0 ^ ((r0 >> 1) & 3)) << 4);
        int k0 = lane & 15;
        int cb0 = wn * 8 + (lane >> 4);
        bA = sbase + SM_B0 + k0 * 256 + ((cb0 ^ (k0 & 7)) << 4);
    }

    float c[4][8][4];
#pragma unroll
    for (int mf = 0; mf < 4; mf++)
#pragma unroll
        for (int nn = 0; nn < 8; nn++)
#pragma unroll
            for (int i = 0; i < 4; i++) c[mf][nn][i] = 0.f;

    // prologue: 3 stages in flight
#pragma unroll
    for (int s = 0; s < STAGES - 1; s++) { issue(s); cp_commit(); }

#pragma unroll 1
    for (int kt = 0; kt < KT; kt++) {
        cp_wait<STAGES - 2>();
        __syncthreads();
        if (kt + STAGES - 1 < KT) issue(kt + STAGES - 1);
        cp_commit();

        const int s = kt & (STAGES - 1);
        const uint32_t sA = aA + s * A_STAGE;
        const uint32_t sB = bA + s * B_STAGE;
#pragma unroll
        for (int kh = 0; kh < 2; kh++) {
            uint32_t a[4][4], b[4][4];
#pragma unroll
            for (int mf = 0; mf < 4; mf++)
                ldsm4(a[mf], (sA + mf * 1024) ^ (kh << 5));
#pragma unroll
            for (int nf = 0; nf < 4; nf++)
                ldsm4t(b[nf], (sB + kh * 4096) ^ (nf << 5));
#pragma unroll
            for (int mf = 0; mf < 4; mf++)
#pragma unroll
                for (int nf = 0; nf < 4; nf++) {
                    mma16816(c[mf][nf * 2 + 0], a[mf], b[nf][0], b[nf][1]);
                    mma16816(c[mf][nf * 2 + 1], a[mf], b[nf][2], b[nf][3]);
                }
        }
    }
    __syncthreads();   // all compute done before slab overlays stage smem

    // ---- epilogue via per-warp smem slab -> wide coalesced stores ----
    float* slab = reinterpret_cast<float*>(smem + wid * SLABB);
    const int er = lane >> 1, ec = (lane & 1) * 32;
#pragma unroll
    for (int mf = 0; mf < 4; mf++) {
#pragma unroll
        for (int nn = 0; nn < 8; nn++)
#pragma unroll
            for (int i = 0; i < 4; i++) {
                float v = c[mf][nn][i];
                if (FIRST) v = gelu_tanh(v);
                slab[(grp + (i >> 1) * 8) * SLABW + nn * 8 + qid * 2 + (i & 1)] = v;
            }
        __syncwarp();
        size_t row = (size_t)e * 1024 + by * 256 + wm * 64 + mf * 16 + er;
        int col = nb * BN + wn * 64 + ec;
        float v[32];
#pragma unroll
        for (int j = 0; j < 8; j++) {
            float4 t4 = *reinterpret_cast<const float4*>(slab + er * SLABW + ec + 4 * j);
            v[4 * j] = t4.x; v[4 * j + 1] = t4.y; v[4 * j + 2] = t4.z; v[4 * j + 3] = t4.w;
        }
        if (FIRST) {
            uint4* dst = reinterpret_cast<uint4*>(g_h + row * FFN + col);
#pragma unroll
            for (int j = 0; j < 4; j++)
                dst[j] = make_uint4(pack2(v[8 * j], v[8 * j + 1]), pack2(v[8 * j + 2], v[8 * j + 3]),
                                    pack2(v[8 * j + 4], v[8 * j + 5]), pack2(v[8 * j + 6], v[8 * j + 7]));
        } else {
            float4* dst = reinterpret_cast<float4*>(g_ye + row * HS + col);
#pragma unroll
            for (int j = 0; j < 8; j++)
                dst[j] = make_float4(v[4 * j], v[4 * j + 1], v[4 * j + 2], v[4 * j + 3]);
        }
        __syncwarp();
    }
}

// ---------------- combine --------------------------------------------------------
__global__ void combine_kernel(const float* __restrict__ bias, float* __restrict__ out) {
    int t = blockIdx.x;
    int j = threadIdx.x;
    float4 acc = reinterpret_cast<const float4*>(bias)[j];
    int p0 = g_pos[t];
    int p1 = g_pos[TOKENS + t];
    float w0 = g_weight[t * 2 + 0], w1 = g_weight[t * 2 + 1];
    if (p0 >= 0) {
        float4 v = reinterpret_cast<const float4*>(g_ye + (size_t)p0 * HS)[j];
        acc.x += w0 * v.x; acc.y += w0 * v.y; acc.z += w0 * v.z; acc.w += w0 * v.w;
    }
    if (p1 >= 0) {
        float4 v = reinterpret_cast<const float4*>(g_ye + (size_t)p1 * HS)[j];
        acc.x += w1 * v.x; acc.y += w1 * v.y; acc.z += w1 * v.z; acc.w += w1 * v.w;
    }
    reinterpret_cast<float4*>(out + (size_t)t * HS)[j] = acc;
}

// ---------------- launch -----------------------------------------------------------
extern "C" void kernel_launch(void* const* d_in, const int* in_sizes, int n_in,
                              void* d_out, int out_size) {
    const float* x    = (const float*)d_in[0];
    const float* rw   = (const float*)d_in[1];
    const float* w1   = (const float*)d_in[2];
    const float* w2   = (const float*)d_in[3];
    const float* bias = (const float*)d_in[4];
    float* out = (float*)d_out;

    cudaFuncSetAttribute(moe_gemm<true>,  cudaFuncAttributeMaxDynamicSharedMemorySize, SMEM_TOT);
    cudaFuncSetAttribute(moe_gemm<false>, cudaFuncAttributeMaxDynamicSharedMemorySize, SMEM_TOT);

    __half* w1h; cudaGetSymbolAddress((void**)&w1h, g_w1h);
    __half* w2h; cudaGetSymbolAddress((void**)&w2h, g_w2h);
    __half* xa;  cudaGetSymbolAddress((void**)&xa,  g_xa);
    __half* hh;  cudaGetSymbolAddress((void**)&hh,  g_h);

    const int WN4 = NE * HS * FFN / 4;
    convert_w<<<WN4 / 256, 256>>>(w1, w1h);
    convert_w<<<WN4 / 256, 256>>>(w2, w2h);
    router_kernel<<<TOKENS / 8, 256>>>(x, rw);
    dispatch_kernel<<<1, 512>>>();
    gather_x<<<NE * 1024, 256>>>(x);
    moe_gemm<true ><<<dim3(FFN / BN, 1024 / BM, NE), NTH, SMEM_TOT>>>(xa, w1h);
    moe_gemm<false><<<dim3(HS  / BN, 1024 / BM, NE), NTH, SMEM_TOT>>>(hh, w2h);
    combine_kernel<<<TOKENS, 256>>>(bias, out);
}

// round 6
// speedup vs baseline: 2.0095x; 1.0364x over previous
#include <cuda_runtime.h>
#include <cuda_fp16.h>
#include <cstdint>
#include <math.h>

#define TOKENS 4096
#define HS 1024
#define FFN 4096
#define NE 8
#define CAP 512

// ---------------- scratch (static device globals; no allocations) -----------
__device__ int    g_expert[TOKENS * 2];
__device__ float  g_weight[TOKENS * 2];
__device__ int    g_rows[NE * 1024];
__device__ int    g_pos[2 * TOKENS];
__device__ __half g_xa[(size_t)NE * 1024 * HS];    // gathered A for gemm1 (fp16)
__device__ __half g_w1h[(size_t)NE * HS * FFN];    // w1 fp16
__device__ __half g_w2h[(size_t)NE * FFN * HS];    // w2 fp16
__device__ __half g_h[(size_t)NE * 1024 * FFN];    // gemm1 out fp16
__device__ float  g_ye[(size_t)NE * 1024 * HS];    // gemm2 out f32

// ---------------- GEMM config -------------------------------------------------
#define BM 256
#define BN 128
#define NTH 256
#define A_SUB 16384              // 256 rows x 64B   (one BK=32 subtile)
#define B_SUB 8192               // 32 rows x 256B
#define STAGE_BYTES (2 * A_SUB + 2 * B_SUB)   // 49152 (BK=64 stage)
#define SM_BOFF (2 * A_SUB)      // B offset within a stage
#define NSTG 3
#define SMEM_TOT (NSTG * STAGE_BYTES)         // 147456
#define SLABW 68                 // epilogue slab row width (f32) per warp
#define SLABB (16 * SLABW * 4)   // 4352 bytes per warp

// ---------------- helpers -----------------------------------------------------
__device__ __forceinline__ uint32_t smem_u32(const void* p) {
    uint32_t a;
    asm("{ .reg .u64 t; cvta.to.shared.u64 t, %1; cvt.u32.u64 %0, t; }" : "=r"(a) : "l"(p));
    return a;
}
__device__ __forceinline__ uint32_t pack2(float lo, float hi) {
    __half2 h = __floats2half2_rn(lo, hi);
    return *reinterpret_cast<uint32_t*>(&h);
}
__device__ __forceinline__ void cp16(uint32_t sdst, const void* gsrc) {
    asm volatile("cp.async.cg.shared.global [%0], [%1], 16;" :: "r"(sdst), "l"(gsrc));
}
__device__ __forceinline__ void cp_commit() { asm volatile("cp.async.commit_group;"); }
template <int N> __device__ __forceinline__ void cp_wait() {
    asm volatile("cp.async.wait_group %0;" :: "n"(N));
}
__device__ __forceinline__ void ldsm4(uint32_t r[4], uint32_t addr) {
    asm volatile("ldmatrix.sync.aligned.m8n8.x4.shared.b16 {%0,%1,%2,%3}, [%4];"
                 : "=r"(r[0]), "=r"(r[1]), "=r"(r[2]), "=r"(r[3]) : "r"(addr));
}
__device__ __forceinline__ void ldsm4t(uint32_t r[4], uint32_t addr) {
    asm volatile("ldmatrix.sync.aligned.m8n8.x4.trans.shared.b16 {%0,%1,%2,%3}, [%4];"
                 : "=r"(r[0]), "=r"(r[1]), "=r"(r[2]), "=r"(r[3]) : "r"(addr));
}
__device__ __forceinline__ void mma16816(float c[4], const uint32_t a[4],
                                         uint32_t b0, uint32_t b1) {
    asm volatile(
        "mma.sync.aligned.m16n8k16.row.col.f32.f16.f16.f32 "
        "{%0,%1,%2,%3}, {%4,%5,%6,%7}, {%8,%9}, {%0,%1,%2,%3};"
        : "+f"(c[0]), "+f"(c[1]), "+f"(c[2]), "+f"(c[3])
        : "r"(a[0]), "r"(a[1]), "r"(a[2]), "r"(a[3]), "r"(b0), "r"(b1));
}
__device__ __forceinline__ float gelu_tanh(float v) {
    float v3 = v * v * v;
    return 0.5f * v * (1.0f + tanhf(0.7978845608028654f * (v + 0.044715f * v3)));
}

// ---------------- router (validated) -------------------------------------------
__global__ void router_kernel(const float* __restrict__ x, const float* __restrict__ rw) {
    int warp = threadIdx.x >> 5, lane = threadIdx.x & 31;
    int t = blockIdx.x * 8 + warp;
    const float* xr = x + (size_t)t * HS;
    float acc[NE];
#pragma unroll
    for (int e = 0; e < NE; e++) acc[e] = 0.f;
    for (int j = lane; j < HS; j += 32) {
        float xv = xr[j];
        const float4* r4 = reinterpret_cast<const float4*>(rw + (size_t)j * NE);
        float4 ra = r4[0], rb = r4[1];
        acc[0] += xv * ra.x; acc[1] += xv * ra.y; acc[2] += xv * ra.z; acc[3] += xv * ra.w;
        acc[4] += xv * rb.x; acc[5] += xv * rb.y; acc[6] += xv * rb.z; acc[7] += xv * rb.w;
    }
#pragma unroll
    for (int o = 16; o > 0; o >>= 1)
#pragma unroll
        for (int e = 0; e < NE; e++) acc[e] += __shfl_xor_sync(0xffffffffu, acc[e], o);
    if (lane == 0) {
        float m = acc[0];
#pragma unroll
        for (int e = 1; e < NE; e++) m = fmaxf(m, acc[e]);
        float s[NE]; float sum = 0.f;
#pragma unroll
        for (int e = 0; e < NE; e++) { s[e] = expf(acc[e] - m); sum += s[e]; }
        float inv = 1.f / sum;
        int e0 = 0; float m0 = s[0];
#pragma unroll
        for (int e = 1; e < NE; e++) if (s[e] > m0) { m0 = s[e]; e0 = e; }
        int e1 = -1; float m1 = -1.f;
#pragma unroll
        for (int e = 0; e < NE; e++) if (e != e0 && s[e] > m1) { m1 = s[e]; e1 = e; }
        g_expert[t * 2 + 0] = e0; g_expert[t * 2 + 1] = e1;
        g_weight[t * 2 + 0] = m0 * inv; g_weight[t * 2 + 1] = m1 * inv;
    }
}

// ---------------- dispatch: smem-staged ballot scan ------------------------------
__global__ void dispatch_kernel() {
    __shared__ int se[TOKENS * 2];   // 32KB
    for (int i = threadIdx.x; i < TOKENS * 2 / 4; i += 512)
        reinterpret_cast<int4*>(se)[i] = reinterpret_cast<const int4*>(g_expert)[i];
    __syncthreads();

    int w = threadIdx.x >> 5, lane = threadIdx.x & 31;
    int k = w >> 3, e = w & 7;
    int count = 0;
    for (int base = 0; base < TOKENS; base += 32) {
        int t = base + lane;
        bool match = (se[t * 2 + k] == e);
        unsigned mask = __ballot_sync(0xffffffffu, match);
        int r = count + __popc(mask & ((1u << lane) - 1u));
        if (match) {
            if (r < CAP) {
                int slot = k * CAP + r;
                g_rows[e * 1024 + slot] = t;
                g_pos[k * TOKENS + t] = e * 1024 + slot;
            } else {
                g_pos[k * TOKENS + t] = -1;
            }
        }
        count += __popc(mask);
    }
    for (int s = count + lane; s < CAP; s += 32)
        g_rows[e * 1024 + k * CAP + s] = -1;
}

// ---------------- f32 -> fp16 weight convert -------------------------------------
__global__ void convert_w(const float* __restrict__ src, __half* __restrict__ dst) {
    int i = blockIdx.x * blockDim.x + threadIdx.x;
    float4 v = reinterpret_cast<const float4*>(src)[i];
    reinterpret_cast<uint2*>(dst)[i] = make_uint2(pack2(v.x, v.y), pack2(v.z, v.w));
}

// ---------------- gather X -> fp16 A for gemm1 -----------------------------------
__global__ void gather_x(const float* __restrict__ X) {
    int slot = blockIdx.x;
    int tok = g_rows[slot];
    int j = threadIdx.x;
    uint2 h = make_uint2(0u, 0u);
    if (tok >= 0) {
        float4 v = reinterpret_cast<const float4*>(X + (size_t)tok * HS)[j];
        h = make_uint2(pack2(v.x, v.y), pack2(v.z, v.w));
    }
    reinterpret_cast<uint2*>(g_xa + (size_t)slot * HS)[j] = h;
}

// ---------------- fp16 cp.async GEMM: BK=64 stages (2x BK32 subtiles), 3-deep ----
template <bool FIRST>
__global__ void __launch_bounds__(NTH, 1)
moe_gemm(const __half* __restrict__ A0, const __half* __restrict__ W0) {
    constexpr int K = FIRST ? HS : FFN;
    constexpr int N = FIRST ? FFN : HS;
    constexpr int KT2 = K / 64;
    extern __shared__ char smem[];
    const uint32_t sbase = smem_u32(smem);
    const int tid = threadIdx.x, wid = tid >> 5, lane = tid & 31;
    const int e = blockIdx.z, by = blockIdx.y, nb = blockIdx.x;
    const int wm = wid & 3, wn = wid >> 2;          // 4x2 warp grid -> 64x64 per warp
    const int grp = lane >> 2, qid = lane & 3;

    const __half* Abase = A0 + (size_t)(e * 1024 + by * 256) * K;
    const __half* Wbase = W0 + (size_t)e * K * N + nb * BN;

    const __half* aSrc = Abase + (size_t)(tid >> 2) * K + (tid & 3) * 8;
    const uint32_t aDst = sbase + (tid >> 2) * 64 + ((((tid & 3)) ^ (((tid >> 2) >> 1) & 3)) << 4);
    const __half* bSrc = Wbase + (size_t)(tid >> 4) * N + (tid & 15) * 8;
    const uint32_t bDst = sbase + SM_BOFF + (tid >> 4) * 256 + (((tid & 15) ^ ((tid >> 4) & 7)) << 4);

    auto issue = [&](int kt2) {
        const uint32_t st = (uint32_t)(kt2 % NSTG) * STAGE_BYTES;
#pragma unroll
        for (int h = 0; h < 2; h++) {
            const __half* ap = aSrc + kt2 * 64 + h * 32;
#pragma unroll
            for (int p = 0; p < 4; p++)
                cp16(aDst + st + h * A_SUB + p * 4096, ap + (size_t)p * 64 * K);
            const __half* bp = bSrc + (size_t)(kt2 * 64 + h * 32) * N;
#pragma unroll
            for (int p = 0; p < 2; p++)
                cp16(bDst + st + h * B_SUB + p * 4096, bp + (size_t)p * 16 * N);
        }
    };

    uint32_t aA, bA;
    {
        int r0 = wm * 64 + (lane & 15);
        int c0 = lane >> 4;
        aA = sbase + r0 * 64 + ((c0 ^ ((r0 >> 1) & 3)) << 4);
        int k0 = lane & 15;
        int cb0 = wn * 8 + (lane >> 4);
        bA = sbase + SM_BOFF + k0 * 256 + ((cb0 ^ (k0 & 7)) << 4);
    }

    float c[4][8][4];
#pragma unroll
    for (int mf = 0; mf < 4; mf++)
#pragma unroll
        for (int nn = 0; nn < 8; nn++)
#pragma unroll
            for (int i = 0; i < 4; i++) c[mf][nn][i] = 0.f;

    issue(0); cp_commit();
    issue(1); cp_commit();

#pragma unroll 1
    for (int kt2 = 0; kt2 < KT2; kt2++) {
        cp_wait<1>();
        __syncthreads();
        if (kt2 + 2 < KT2) issue(kt2 + 2);
        cp_commit();

        const uint32_t st = (uint32_t)(kt2 % NSTG) * STAGE_BYTES;
#pragma unroll
        for (int h = 0; h < 2; h++) {
            const uint32_t sA = aA + st + h * A_SUB;
            const uint32_t sB = bA + st + h * B_SUB;
#pragma unroll
            for (int kh = 0; kh < 2; kh++) {
                uint32_t a[4][4], b[4][4];
#pragma unroll
                for (int mf = 0; mf < 4; mf++)
                    ldsm4(a[mf], (sA + mf * 1024) ^ (kh << 5));
#pragma unroll
                for (int nf = 0; nf < 4; nf++)
                    ldsm4t(b[nf], (sB + kh * 4096) ^ (nf << 5));
#pragma unroll
                for (int mf = 0; mf < 4; mf++)
#pragma unroll
                    for (int nf = 0; nf < 4; nf++) {
                        mma16816(c[mf][nf * 2 + 0], a[mf], b[nf][0], b[nf][1]);
                        mma16816(c[mf][nf * 2 + 1], a[mf], b[nf][2], b[nf][3]);
                    }
            }
        }
    }
    __syncthreads();   // all compute done before slab overlays stage smem

    float* slab = reinterpret_cast<float*>(smem + wid * SLABB);
    const int er = lane >> 1, ec = (lane & 1) * 32;
#pragma unroll
    for (int mf = 0; mf < 4; mf++) {
#pragma unroll
        for (int nn = 0; nn < 8; nn++)
#pragma unroll
            for (int i = 0; i < 4; i++) {
                float v = c[mf][nn][i];
                if (FIRST) v = gelu_tanh(v);
                slab[(grp + (i >> 1) * 8) * SLABW + nn * 8 + qid * 2 + (i & 1)] = v;
            }
        __syncwarp();
        size_t row = (size_t)e * 1024 + by * 256 + wm * 64 + mf * 16 + er;
        int col = nb * BN + wn * 64 + ec;
        float v[32];
#pragma unroll
        for (int j = 0; j < 8; j++) {
            float4 t4 = *reinterpret_cast<const float4*>(slab + er * SLABW + ec + 4 * j);
            v[4 * j] = t4.x; v[4 * j + 1] = t4.y; v[4 * j + 2] = t4.z; v[4 * j + 3] = t4.w;
        }
        if (FIRST) {
            uint4* dst = reinterpret_cast<uint4*>(g_h + row * FFN + col);
#pragma unroll
            for (int j = 0; j < 4; j++)
                dst[j] = make_uint4(pack2(v[8 * j], v[8 * j + 1]), pack2(v[8 * j + 2], v[8 * j + 3]),
                                    pack2(v[8 * j + 4], v[8 * j + 5]), pack2(v[8 * j + 6], v[8 * j + 7]));
        } else {
            float4* dst = reinterpret_cast<float4*>(g_ye + row * HS + col);
#pragma unroll
            for (int j = 0; j < 8; j++)
                dst[j] = make_float4(v[4 * j], v[4 * j + 1], v[4 * j + 2], v[4 * j + 3]);
        }
        __syncwarp();
    }
}

// ---------------- combine --------------------------------------------------------
__global__ void combine_kernel(const float* __restrict__ bias, float* __restrict__ out) {
    int t = blockIdx.x;
    int j = threadIdx.x;
    float4 acc = reinterpret_cast<const float4*>(bias)[j];
    int p0 = g_pos[t];
    int p1 = g_pos[TOKENS + t];
    float w0 = g_weight[t * 2 + 0], w1 = g_weight[t * 2 + 1];
    if (p0 >= 0) {
        float4 v = reinterpret_cast<const float4*>(g_ye + (size_t)p0 * HS)[j];
        acc.x += w0 * v.x; acc.y += w0 * v.y; acc.z += w0 * v.z; acc.w += w0 * v.w;
    }
    if (p1 >= 0) {
        float4 v = reinterpret_cast<const float4*>(g_ye + (size_t)p1 * HS)[j];
        acc.x += w1 * v.x; acc.y += w1 * v.y; acc.z += w1 * v.z; acc.w += w1 * v.w;
    }
    reinterpret_cast<float4*>(out + (size_t)t * HS)[j] = acc;
}

// ---------------- launch -----------------------------------------------------------
extern "C" void kernel_launch(void* const* d_in, const int* in_sizes, int n_in,
                              void* d_out, int out_size) {
    const float* x    = (const float*)d_in[0];
    const float* rw   = (const float*)d_in[1];
    const float* w1   = (const float*)d_in[2];
    const float* w2   = (const float*)d_in[3];
    const float* bias = (const float*)d_in[4];
    float* out = (float*)d_out;

    cudaFuncSetAttribute(moe_gemm<true>,  cudaFuncAttributeMaxDynamicSharedMemorySize, SMEM_TOT);
    cudaFuncSetAttribute(moe_gemm<false>, cudaFuncAttributeMaxDynamicSharedMemorySize, SMEM_TOT);

    __half* w1h; cudaGetSymbolAddress((void**)&w1h, g_w1h);
    __half* w2h; cudaGetSymbolAddress((void**)&w2h, g_w2h);
    __half* xa;  cudaGetSymbolAddress((void**)&xa,  g_xa);
    __half* hh;  cudaGetSymbolAddress((void**)&hh,  g_h);

    const int WN4 = NE * HS * FFN / 4;
    convert_w<<<WN4 / 256, 256>>>(w1, w1h);
    convert_w<<<WN4 / 256, 256>>>(w2, w2h);
    router_kernel<<<TOKENS / 8, 256>>>(x, rw);
    dispatch_kernel<<<1, 512>>>();
    gather_x<<<NE * 1024, 256>>>(x);
    moe_gemm<true ><<<dim3(FFN / BN, 1024 / BM, NE), NTH, SMEM_TOT>>>(xa, w1h);
    moe_gemm<false><<<dim3(HS  / BN, 1024 / BM, NE), NTH, SMEM_TOT>>>(hh, w2h);
    combine_kernel<<<TOKENS, 256>>>(bias, out);
}

// round 7
// speedup vs baseline: 2.0964x; 1.0432x over previous
#include <cuda_runtime.h>
#include <cuda_fp16.h>
#include <cstdint>
#include <math.h>

#define TOKENS 4096
#define HS 1024
#define FFN 4096
#define NE 8
#define CAP 512

// ---------------- scratch (static device globals; no allocations) -----------
__device__ int    g_expert[TOKENS * 2];
__device__ float  g_weight[TOKENS * 2];
__device__ int    g_rows[NE * 1024];
__device__ int    g_pos[2 * TOKENS];
__device__ __half g_xa[(size_t)NE * 1024 * HS];    // gathered A for gemm1 (fp16)
__device__ __half g_w1h[(size_t)NE * HS * FFN];    // w1 fp16
__device__ __half g_w2h[(size_t)NE * FFN * HS];    // w2 fp16
__device__ __half g_h[(size_t)NE * 1024 * FFN];    // gemm1 out fp16
__device__ float  g_ye[(size_t)NE * 1024 * HS];    // gemm2 out f32

// ---------------- GEMM config -------------------------------------------------
#define BN 128
#define NTH 256
#define NSTG 3
#define SLABW 68
#define SLABB (16 * SLABW * 4)

// ---------------- helpers -----------------------------------------------------
__device__ __forceinline__ uint32_t smem_u32(const void* p) {
    uint32_t a;
    asm("{ .reg .u64 t; cvta.to.shared.u64 t, %1; cvt.u32.u64 %0, t; }" : "=r"(a) : "l"(p));
    return a;
}
__device__ __forceinline__ uint32_t pack2(float lo, float hi) {
    __half2 h = __floats2half2_rn(lo, hi);
    return *reinterpret_cast<uint32_t*>(&h);
}
__device__ __forceinline__ void cp16(uint32_t sdst, const void* gsrc) {
    asm volatile("cp.async.cg.shared.global [%0], [%1], 16;" :: "r"(sdst), "l"(gsrc));
}
__device__ __forceinline__ void cp_commit() { asm volatile("cp.async.commit_group;"); }
template <int N> __device__ __forceinline__ void cp_wait() {
    asm volatile("cp.async.wait_group %0;" :: "n"(N));
}
__device__ __forceinline__ void ldsm4(uint32_t r[4], uint32_t addr) {
    asm volatile("ldmatrix.sync.aligned.m8n8.x4.shared.b16 {%0,%1,%2,%3}, [%4];"
                 : "=r"(r[0]), "=r"(r[1]), "=r"(r[2]), "=r"(r[3]) : "r"(addr));
}
__device__ __forceinline__ void ldsm4t(uint32_t r[4], uint32_t addr) {
    asm volatile("ldmatrix.sync.aligned.m8n8.x4.trans.shared.b16 {%0,%1,%2,%3}, [%4];"
                 : "=r"(r[0]), "=r"(r[1]), "=r"(r[2]), "=r"(r[3]) : "r"(addr));
}
__device__ __forceinline__ void mma16816(float c[4], const uint32_t a[4],
                                         uint32_t b0, uint32_t b1) {
    asm volatile(
        "mma.sync.aligned.m16n8k16.row.col.f32.f16.f16.f32 "
        "{%0,%1,%2,%3}, {%4,%5,%6,%7}, {%8,%9}, {%0,%1,%2,%3};"
        : "+f"(c[0]), "+f"(c[1]), "+f"(c[2]), "+f"(c[3])
        : "r"(a[0]), "r"(a[1]), "r"(a[2]), "r"(a[3]), "r"(b0), "r"(b1));
}
__device__ __forceinline__ float gelu_tanh(float v) {
    float v3 = v * v * v;
    return 0.5f * v * (1.0f + tanhf(0.7978845608028654f * (v + 0.044715f * v3)));
}

// ---------------- router (validated) -------------------------------------------
__global__ void router_kernel(const float* __restrict__ x, const float* __restrict__ rw) {
    int warp = threadIdx.x >> 5, lane = threadIdx.x & 31;
    int t = blockIdx.x * 8 + warp;
    const float* xr = x + (size_t)t * HS;
    float acc[NE];
#pragma unroll
    for (int e = 0; e < NE; e++) acc[e] = 0.f;
    for (int j = lane; j < HS; j += 32) {
        float xv = xr[j];
        const float4* r4 = reinterpret_cast<const float4*>(rw + (size_t)j * NE);
        float4 ra = r4[0], rb = r4[1];
        acc[0] += xv * ra.x; acc[1] += xv * ra.y; acc[2] += xv * ra.z; acc[3] += xv * ra.w;
        acc[4] += xv * rb.x; acc[5] += xv * rb.y; acc[6] += xv * rb.z; acc[7] += xv * rb.w;
    }
#pragma unroll
    for (int o = 16; o > 0; o >>= 1)
#pragma unroll
        for (int e = 0; e < NE; e++) acc[e] += __shfl_xor_sync(0xffffffffu, acc[e], o);
    if (lane == 0) {
        float m = acc[0];
#pragma unroll
        for (int e = 1; e < NE; e++) m = fmaxf(m, acc[e]);
        float s[NE]; float sum = 0.f;
#pragma unroll
        for (int e = 0; e < NE; e++) { s[e] = expf(acc[e] - m); sum += s[e]; }
        float inv = 1.f / sum;
        int e0 = 0; float m0 = s[0];
#pragma unroll
        for (int e = 1; e < NE; e++) if (s[e] > m0) { m0 = s[e]; e0 = e; }
        int e1 = -1; float m1 = -1.f;
#pragma unroll
        for (int e = 0; e < NE; e++) if (e != e0 && s[e] > m1) { m1 = s[e]; e1 = e; }
        g_expert[t * 2 + 0] = e0; g_expert[t * 2 + 1] = e1;
        g_weight[t * 2 + 0] = m0 * inv; g_weight[t * 2 + 1] = m1 * inv;
    }
}

// ---------------- dispatch: two-phase (count half0 || rank halves) --------------
__global__ void dispatch_kernel() {
    __shared__ int se[TOKENS * 2];   // 32KB
    __shared__ int chalf[16];
    for (int i = threadIdx.x; i < TOKENS * 2 / 4; i += 1024)
        reinterpret_cast<int4*>(se)[i] = reinterpret_cast<const int4*>(g_expert)[i];
    __syncthreads();

    int w = threadIdx.x >> 5, lane = threadIdx.x & 31;
    int pair = w >> 1, h = w & 1;          // 16 (k,e) pairs x 2 halves
    int k = pair >> 3, e = pair & 7;

    if (h == 0) {       // count matches in first half (parallel, no serial chain)
        int c = 0;
        for (int t = lane; t < TOKENS / 2; t += 32)
            c += (se[t * 2 + k] == e);
#pragma unroll
        for (int o = 16; o > 0; o >>= 1) c += __shfl_xor_sync(0xffffffffu, c, o);
        if (lane == 0) chalf[pair] = c;
    }
    __syncthreads();

    int count = h ? chalf[pair] : 0;
    const int base0 = h * (TOKENS / 2);
    for (int base = base0; base < base0 + TOKENS / 2; base += 32) {
        int t = base + lane;
        bool match = (se[t * 2 + k] == e);
        unsigned mask = __ballot_sync(0xffffffffu, match);
        int r = count + __popc(mask & ((1u << lane) - 1u));
        if (match) {
            if (r < CAP) {
                int slot = k * CAP + r;
                g_rows[e * 1024 + slot] = t;
                g_pos[k * TOKENS + t] = e * 1024 + slot;
            } else {
                g_pos[k * TOKENS + t] = -1;
            }
        }
        count += __popc(mask);
    }
    if (h == 1)      // this warp's final count == total for (k,e)
        for (int s = count + lane; s < CAP; s += 32)
            g_rows[e * 1024 + k * CAP + s] = -1;
}

// ---------------- f32 -> fp16 weight convert -------------------------------------
__global__ void convert_w(const float* __restrict__ src, __half* __restrict__ dst) {
    int i = blockIdx.x * blockDim.x + threadIdx.x;
    float4 v = reinterpret_cast<const float4*>(src)[i];
    reinterpret_cast<uint2*>(dst)[i] = make_uint2(pack2(v.x, v.y), pack2(v.z, v.w));
}

// ---------------- gather X -> fp16 A for gemm1 -----------------------------------
__global__ void gather_x(const float* __restrict__ X) {
    int slot = blockIdx.x;
    int tok = g_rows[slot];
    int j = threadIdx.x;
    uint2 h = make_uint2(0u, 0u);
    if (tok >= 0) {
        float4 v = reinterpret_cast<const float4*>(X + (size_t)tok * HS)[j];
        h = make_uint2(pack2(v.x, v.y), pack2(v.z, v.w));
    }
    reinterpret_cast<uint2*>(g_xa + (size_t)slot * HS)[j] = h;
}

// ---------------- fp16 cp.async GEMM, parametrized BM ----------------------------
// FIRST(BMT=256,MF=4): g_h = fp16(gelu(g_xa @ w1h));  else(BMT=128,MF=2): g_ye = g_h @ w2h
template <bool FIRST, int BMT, int MF>
__global__ void __launch_bounds__(NTH, FIRST ? 1 : 2)
moe_gemm(const __half* __restrict__ A0, const __half* __restrict__ W0) {
    constexpr int K = FIRST ? HS : FFN;
    constexpr int N = FIRST ? FFN : HS;
    constexpr int KT2 = K / 64;
    constexpr int A_SUB = BMT * 64;          // BK=32 subtile bytes for A
    constexpr int B_SUB = 8192;
    constexpr int STAGE = 2 * A_SUB + 2 * B_SUB;
    constexpr int SM_BOFF = 2 * A_SUB;
    extern __shared__ char smem[];
    const uint32_t sbase = smem_u32(smem);
    const int tid = threadIdx.x, wid = tid >> 5, lane = tid & 31;
    const int e = blockIdx.z, by = blockIdx.y, nb = blockIdx.x;
    const int wm = wid & 3, wn = wid >> 2;          // 4x2 warps: (16*MF) x 64 per warp
    const int grp = lane >> 2, qid = lane & 3;

    const __half* Abase = A0 + (size_t)(e * 1024 + by * BMT) * K;
    const __half* Wbase = W0 + (size_t)e * K * N + nb * BN;

    const __half* aSrc = Abase + (size_t)(tid >> 2) * K + (tid & 3) * 8;
    const uint32_t aDst = sbase + (tid >> 2) * 64 + ((((tid & 3)) ^ (((tid >> 2) >> 1) & 3)) << 4);
    const __half* bSrc = Wbase + (size_t)(tid >> 4) * N + (tid & 15) * 8;
    const uint32_t bDst = sbase + SM_BOFF + (tid >> 4) * 256 + (((tid & 15) ^ ((tid >> 4) & 7)) << 4);

    auto issue = [&](int kt2) {
        const uint32_t st = (uint32_t)(kt2 % NSTG) * STAGE;
#pragma unroll
        for (int h = 0; h < 2; h++) {
            const __half* ap = aSrc + kt2 * 64 + h * 32;
#pragma unroll
            for (int p = 0; p < MF; p++)
                cp16(aDst + st + h * A_SUB + p * 4096, ap + (size_t)p * 64 * K);
            const __half* bp = bSrc + (size_t)(kt2 * 64 + h * 32) * N;
#pragma unroll
            for (int p = 0; p < 2; p++)
                cp16(bDst + st + h * B_SUB + p * 4096, bp + (size_t)p * 16 * N);
        }
    };

    uint32_t aA, bA;
    {
        int r0 = wm * (16 * MF) + (lane & 15);
        int c0 = lane >> 4;
        aA = sbase + r0 * 64 + ((c0 ^ ((r0 >> 1) & 3)) << 4);
        int k0 = lane & 15;
        int cb0 = wn * 8 + (lane >> 4);
        bA = sbase + SM_BOFF + k0 * 256 + ((cb0 ^ (k0 & 7)) << 4);
    }

    float c[MF][8][4];
#pragma unroll
    for (int mf = 0; mf < MF; mf++)
#pragma unroll
        for (int nn = 0; nn < 8; nn++)
#pragma unroll
            for (int i = 0; i < 4; i++) c[mf][nn][i] = 0.f;

    issue(0); cp_commit();
    issue(1); cp_commit();

#pragma unroll 1
    for (int kt2 = 0; kt2 < KT2; kt2++) {
        cp_wait<1>();
        __syncthreads();
        if (kt2 + 2 < KT2) issue(kt2 + 2);
        cp_commit();

        const uint32_t st = (uint32_t)(kt2 % NSTG) * STAGE;
#pragma unroll
        for (int h = 0; h < 2; h++) {
            const uint32_t sA = aA + st + h * A_SUB;
            const uint32_t sB = bA + st + h * B_SUB;
#pragma unroll
            for (int kh = 0; kh < 2; kh++) {
                uint32_t a[MF][4], b[4][4];
#pragma unroll
                for (int mf = 0; mf < MF; mf++)
                    ldsm4(a[mf], (sA + mf * 1024) ^ (kh << 5));
#pragma unroll
                for (int nf = 0; nf < 4; nf++)
                    ldsm4t(b[nf], (sB + kh * 4096) ^ (nf << 5));
#pragma unroll
                for (int mf = 0; mf < MF; mf++)
#pragma unroll
                    for (int nf = 0; nf < 4; nf++) {
                        mma16816(c[mf][nf * 2 + 0], a[mf], b[nf][0], b[nf][1]);
                        mma16816(c[mf][nf * 2 + 1], a[mf], b[nf][2], b[nf][3]);
                    }
            }
        }
    }
    __syncthreads();

    float* slab = reinterpret_cast<float*>(smem + wid * SLABB);
    const int er = lane >> 1, ec = (lane & 1) * 32;
#pragma unroll
    for (int mf = 0; mf < MF; mf++) {
#pragma unroll
        for (int nn = 0; nn < 8; nn++)
#pragma unroll
            for (int i = 0; i < 4; i++) {
                float v = c[mf][nn][i];
                if (FIRST) v = gelu_tanh(v);
                slab[(grp + (i >> 1) * 8) * SLABW + nn * 8 + qid * 2 + (i & 1)] = v;
            }
        __syncwarp();
        size_t row = (size_t)e * 1024 + by * BMT + wm * (16 * MF) + mf * 16 + er;
        int col = nb * BN + wn * 64 + ec;
        float v[32];
#pragma unroll
        for (int j = 0; j < 8; j++) {
            float4 t4 = *reinterpret_cast<const float4*>(slab + er * SLABW + ec + 4 * j);
            v[4 * j] = t4.x; v[4 * j + 1] = t4.y; v[4 * j + 2] = t4.z; v[4 * j + 3] = t4.w;
        }
        if (FIRST) {
            uint4* dst = reinterpret_cast<uint4*>(g_h + row * FFN + col);
#pragma unroll
            for (int j = 0; j < 4; j++)
                dst[j] = make_uint4(pack2(v[8 * j], v[8 * j + 1]), pack2(v[8 * j + 2], v[8 * j + 3]),
                                    pack2(v[8 * j + 4], v[8 * j + 5]), pack2(v[8 * j + 6], v[8 * j + 7]));
        } else {
            float4* dst = reinterpret_cast<float4*>(g_ye + row * HS + col);
#pragma unroll
            for (int j = 0; j < 8; j++)
                dst[j] = make_float4(v[4 * j], v[4 * j + 1], v[4 * j + 2], v[4 * j + 3]);
        }
        __syncwarp();
    }
}

// ---------------- combine --------------------------------------------------------
__global__ void combine_kernel(const float* __restrict__ bias, float* __restrict__ out) {
    int t = blockIdx.x;
    int j = threadIdx.x;
    float4 acc = reinterpret_cast<const float4*>(bias)[j];
    int p0 = g_pos[t];
    int p1 = g_pos[TOKENS + t];
    float w0 = g_weight[t * 2 + 0], w1 = g_weight[t * 2 + 1];
    if (p0 >= 0) {
        float4 v = reinterpret_cast<const float4*>(g_ye + (size_t)p0 * HS)[j];
        acc.x += w0 * v.x; acc.y += w0 * v.y; acc.z += w0 * v.z; acc.w += w0 * v.w;
    }
    if (p1 >= 0) {
        float4 v = reinterpret_cast<const float4*>(g_ye + (size_t)p1 * HS)[j];
        acc.x += w1 * v.x; acc.y += w1 * v.y; acc.z += w1 * v.z; acc.w += w1 * v.w;
    }
    reinterpret_cast<float4*>(out + (size_t)t * HS)[j] = acc;
}

// ---------------- launch -----------------------------------------------------------
#define SMEM1 (NSTG * (2 * 256 * 64 + 2 * 8192))   // 147456
#define SMEM2 (NSTG * (2 * 128 * 64 + 2 * 8192))   // 98304

extern "C" void kernel_launch(void* const* d_in, const int* in_sizes, int n_in,
                              void* d_out, int out_size) {
    const float* x    = (const float*)d_in[0];
    const float* rw   = (const float*)d_in[1];
    const float* w1   = (const float*)d_in[2];
    const float* w2   = (const float*)d_in[3];
    const float* bias = (const float*)d_in[4];
    float* out = (float*)d_out;

    static cudaStream_t s2 = nullptr;
    static cudaEvent_t evA = nullptr, evB = nullptr;
    if (s2 == nullptr) {
        cudaStreamCreateWithFlags(&s2, cudaStreamNonBlocking);
        cudaEventCreateWithFlags(&evA, cudaEventDisableTiming);
        cudaEventCreateWithFlags(&evB, cudaEventDisableTiming);
    }

    cudaFuncSetAttribute((const void*)moe_gemm<true, 256, 4>,
                         cudaFuncAttributeMaxDynamicSharedMemorySize, SMEM1);
    cudaFuncSetAttribute((const void*)moe_gemm<false, 128, 2>,
                         cudaFuncAttributeMaxDynamicSharedMemorySize, SMEM2);

    __half* w1h; cudaGetSymbolAddress((void**)&w1h, g_w1h);
    __half* w2h; cudaGetSymbolAddress((void**)&w2h, g_w2h);
    __half* xa;  cudaGetSymbolAddress((void**)&xa,  g_xa);
    __half* hh;  cudaGetSymbolAddress((void**)&hh,  g_h);

    // fork: routing chain on s2, weight converts on main stream
    cudaEventRecord(evA, 0);
    cudaStreamWaitEvent(s2, evA, 0);
    router_kernel<<<TOKENS / 8, 256, 0, s2>>>(x, rw);
    dispatch_kernel<<<1, 1024, 0, s2>>>();
    gather_x<<<NE * 1024, 256, 0, s2>>>(x);
    cudaEventRecord(evB, s2);

    const int WN4 = NE * HS * FFN / 4;
    convert_w<<<WN4 / 256, 256>>>(w1, w1h);
    convert_w<<<WN4 / 256, 256>>>(w2, w2h);
    cudaStreamWaitEvent(0, evB, 0);

    moe_gemm<true, 256, 4><<<dim3(FFN / BN, 1024 / 256, NE), NTH, SMEM1>>>(xa, w1h);
    moe_gemm<false, 128, 2><<<dim3(HS / BN, 1024 / 128, NE), NTH, SMEM2>>>(hh, w2h);
    combine_kernel<<<TOKENS, 256>>>(bias, out);
}